// round 12
// baseline (speedup 1.0000x reference)
#include <cuda_runtime.h>
#include <cuda_bf16.h>
#include <cuda_pipeline.h>
#include <cstdint>

// OverlapPatchEmbed: x (B=64, C=3, H=224, W=224) f32 -> out (B, 729, C, 256) f32
// out[b][pi*27+pj][c][r*16+s] = x[b][c][pi*8+r][pj*8+s]
//
// Triple-band (block = (b, c, g), pi = 3g..3g+2), smem-staged:
//  - TPB=512, natural pitch 56 (no padding; the LDS.128 pattern
//    (row*56 + pj*2 + s4) is conflict-free per 8-lane phase) -> 28.7KB smem,
//    4 CTAs/SM x 512 thr = 2048 resident threads (regs 32 -> RF exactly full).
//  - load: contiguous 32 rows once via cp.async (LDGSTS.128)
//  - store: 3 bands, fully coalesced streaming STG.128 (__stcs)

namespace {
constexpr int B  = 64;
constexpr int C  = 3;
constexpr int H  = 224;
constexpr int W  = 224;      // 56 float4 per row
constexpr int N  = 27;
constexpr int G  = 9;        // pi groups of 3
constexpr int TPB = 512;

constexpr int W4      = W / 4;          // 56 = natural smem pitch (conflict-free)
constexpr int GROWS   = 32;             // rows per 3-band group
constexpr int LOAD_V  = GROWS * W4;     // 1792 float4 per block
constexpr int STORE_V = N * 64;         // 1728 float4 per band
constexpr int NBLOCKS = B * C * G;      // 1728

constexpr int LK = 4;                   // ceil(1792/512)
constexpr int SK = 4;                   // ceil(1728/512)
}

__global__ __launch_bounds__(TPB, 4)
void overlap_patch_kernel(const float4* __restrict__ x, float4* __restrict__ out)
{
    __shared__ float4 s[GROWS * W4];    // 28672 bytes, natural layout

    const int bx  = blockIdx.x;
    const int g   = bx % G;
    const int c   = (bx / G) % C;
    const int b   = bx / (G * C);
    const int tid = threadIdx.x;
    const int pi0 = g * 3;

    // ---- load phase: 32 contiguous rows -> smem via LDGSTS (identity layout) ----
    const int in_base = ((b * C + c) * H + pi0 * 8) * W4;   // float4 index
    #pragma unroll
    for (int k = 0; k < LK; k++) {
        int i = tid + k * TPB;
        if (i < LOAD_V)
            __pipeline_memcpy_async(&s[i], &x[in_base + i], 16);
    }
    __pipeline_commit();
    __pipeline_wait_prior(0);
    __syncthreads();

    // ---- store phase: 3 bands, each fully coalesced streaming STG.128 ----
    #pragma unroll
    for (int sub = 0; sub < 3; sub++) {
        const int pi  = pi0 + sub;
        const int ob0 = ((b * (N * N) + pi * N) * C + c) * 64;
        const int srow0 = sub * 8;             // smem row offset of this band

        float4 sv[SK];
        #pragma unroll
        for (int k = 0; k < SK; k++) {
            int j = tid + k * TPB;
            if (j < STORE_V) {
                int pj = j >> 6;
                int q  = j & 63;
                int r  = q >> 2;
                int s4 = q & 3;
                sv[k] = s[(srow0 + r) * W4 + pj * 2 + s4];
            }
        }
        #pragma unroll
        for (int k = 0; k < SK; k++) {
            int j = tid + k * TPB;
            if (j < STORE_V) {
                int pj = j >> 6;
                int q  = j & 63;
                __stcs(&out[ob0 + pj * (C * 64) + q], sv[k]);
            }
        }
    }
}

extern "C" void kernel_launch(void* const* d_in, const int* in_sizes, int n_in,
                              void* d_out, int out_size)
{
    const float4* x = (const float4*)d_in[0];
    float4* out = (float4*)d_out;
    overlap_patch_kernel<<<NBLOCKS, TPB>>>(x, out);
}

// round 13
// speedup vs baseline: 1.0077x; 1.0077x over previous
#include <cuda_runtime.h>
#include <cuda_bf16.h>
#include <cstdint>

// OverlapPatchEmbed: x (B=64, C=3, H=224, W=224) f32 -> out (B, 729, C, 256) f32
// out[b][pi*27+pj][c][r*16+s] = x[b][c][pi*8+r][pj*8+s]
//
// Triple-band (block = (b, c, g), pi = 3g..3g+2), smem-staged:
//  - load: ONE cp.async.bulk (TMA 1D) of 28672B per block, mbarrier
//    completion -> zero load-side L1tex wavefronts, zero load registers.
//  - store: 3 bands, conflict-free LDS.128 (natural pitch 56) +
//    fully coalesced streaming STG.128 (__stcs).

namespace {
constexpr int B  = 64;
constexpr int C  = 3;
constexpr int H  = 224;
constexpr int W  = 224;      // 56 float4 per row
constexpr int N  = 27;
constexpr int G  = 9;        // pi groups of 3
constexpr int TPB = 512;

constexpr int W4      = W / 4;          // 56 = natural smem pitch (conflict-free)
constexpr int GROWS   = 32;             // rows per 3-band group
constexpr int LOAD_BYTES = GROWS * W4 * 16;  // 28672
constexpr int STORE_V = N * 64;         // 1728 float4 per band
constexpr int NBLOCKS = B * C * G;      // 1728
constexpr int SK = 4;                   // ceil(1728/512)
}

__global__ __launch_bounds__(TPB, 4)
void overlap_patch_kernel(const float4* __restrict__ x, float4* __restrict__ out)
{
    __shared__ alignas(128) float4 s[GROWS * W4];   // 28672 bytes
    __shared__ alignas(8) unsigned long long mbar;

    const int bx  = blockIdx.x;
    const int g   = bx % G;
    const int c   = (bx / G) % C;
    const int b   = bx / (G * C);
    const int tid = threadIdx.x;
    const int pi0 = g * 3;

    // smem addresses as u32
    uint32_t s_addr, mbar_addr;
    asm("{ .reg .u64 t; cvta.to.shared.u64 t, %1; cvt.u32.u64 %0, t; }"
        : "=r"(s_addr) : "l"((void*)s));
    asm("{ .reg .u64 t; cvta.to.shared.u64 t, %1; cvt.u32.u64 %0, t; }"
        : "=r"(mbar_addr) : "l"((void*)&mbar));

    // ---- init mbarrier, then issue one bulk load ----
    if (tid == 0) {
        asm volatile("mbarrier.init.shared.b64 [%0], 1;" :: "r"(mbar_addr) : "memory");
    }
    __syncthreads();

    if (tid == 0) {
        asm volatile("mbarrier.arrive.expect_tx.shared.b64 _, [%0], %1;"
                     :: "r"(mbar_addr), "r"((uint32_t)LOAD_BYTES) : "memory");
        const int in_base = ((b * C + c) * H + pi0 * 8) * W4;   // float4 index
        asm volatile(
            "cp.async.bulk.shared::cta.global.mbarrier::complete_tx::bytes "
            "[%0], [%1], %2, [%3];"
            :: "r"(s_addr), "l"(x + in_base), "r"((uint32_t)LOAD_BYTES),
               "r"(mbar_addr) : "memory");
    }

    // ---- wait for the bulk load (acquire orders smem reads after TMA writes) ----
    {
        uint32_t done;
        asm volatile(
            "{\n\t"
            ".reg .pred p;\n\t"
            "mbarrier.try_wait.parity.acquire.cta.shared::cta.b64 p, [%1], 0;\n\t"
            "selp.b32 %0, 1, 0, p;\n\t"
            "}"
            : "=r"(done) : "r"(mbar_addr) : "memory");
        if (!done) {
            asm volatile(
                "{\n\t"
                ".reg .pred P1;\n\t"
                "WAIT_LOOP:\n\t"
                "mbarrier.try_wait.parity.acquire.cta.shared::cta.b64 P1, [%0], 0, 0x989680;\n\t"
                "@P1 bra.uni WAIT_DONE;\n\t"
                "bra.uni WAIT_LOOP;\n\t"
                "WAIT_DONE:\n\t"
                "}"
                :: "r"(mbar_addr) : "memory");
        }
    }
    __syncthreads();

    // ---- store phase: 3 bands, each fully coalesced streaming STG.128 ----
    #pragma unroll
    for (int sub = 0; sub < 3; sub++) {
        const int pi  = pi0 + sub;
        const int ob0 = ((b * (N * N) + pi * N) * C + c) * 64;
        const int srow0 = sub * 8;             // smem row offset of this band

        float4 sv[SK];
        #pragma unroll
        for (int k = 0; k < SK; k++) {
            int j = tid + k * TPB;
            if (j < STORE_V) {
                int pj = j >> 6;
                int q  = j & 63;
                int r  = q >> 2;
                int s4 = q & 3;
                sv[k] = s[(srow0 + r) * W4 + pj * 2 + s4];
            }
        }
        #pragma unroll
        for (int k = 0; k < SK; k++) {
            int j = tid + k * TPB;
            if (j < STORE_V) {
                int pj = j >> 6;
                int q  = j & 63;
                __stcs(&out[ob0 + pj * (C * 64) + q], sv[k]);
            }
        }
    }
}

extern "C" void kernel_launch(void* const* d_in, const int* in_sizes, int n_in,
                              void* d_out, int out_size)
{
    const float4* x = (const float4*)d_in[0];
    float4* out = (float4*)d_out;
    overlap_patch_kernel<<<NBLOCKS, TPB>>>(x, out);
}